// round 1
// baseline (speedup 1.0000x reference)
#include <cuda_runtime.h>
#include <cstdint>

#define NNODE 50000
#define NEDGE 1600000

// ---------------- device scratch (no allocations allowed) ----------------
__device__ float g_e1[(size_t)NEDGE * 32];   // lrelu(e1)
__device__ float g_e2[(size_t)NEDGE * 32];   // lrelu(e2)
__device__ float g_n1[(size_t)NNODE * 32];
__device__ float g_n2[(size_t)NNODE * 32];
__device__ float g_ns1[(size_t)NNODE * 32];
__device__ float g_ns2[(size_t)NNODE * 32];
__device__ float g_ns3[(size_t)NNODE * 32];
__device__ float g_inv[NNODE];
__device__ int   g_cnt[NNODE];

__device__ __forceinline__ float lrelu(float x) { return x > 0.f ? x : 0.2f * x; }

__device__ __forceinline__ void fma32(float (&acc)[32], float hv, const float* __restrict__ wrow) {
#pragma unroll
    for (int j4 = 0; j4 < 8; j4++) {
        float4 w = *(const float4*)(wrow + j4 * 4);
        acc[j4 * 4 + 0] = fmaf(hv, w.x, acc[j4 * 4 + 0]);
        acc[j4 * 4 + 1] = fmaf(hv, w.y, acc[j4 * 4 + 1]);
        acc[j4 * 4 + 2] = fmaf(hv, w.z, acc[j4 * 4 + 2]);
        acc[j4 * 4 + 3] = fmaf(hv, w.w, acc[j4 * 4 + 3]);
    }
}

// ---------------- setup kernels ----------------
__global__ void zero_kernel() {
    int stride = gridDim.x * blockDim.x;
    int i0 = blockIdx.x * blockDim.x + threadIdx.x;
    for (int v = i0; v < NNODE * 32; v += stride) {
        g_ns1[v] = 0.f; g_ns2[v] = 0.f; g_ns3[v] = 0.f;
    }
    for (int v = i0; v < NNODE; v += stride) g_cnt[v] = 0;
}

__global__ void count_kernel(const int* __restrict__ row) {
    int e = blockIdx.x * 256 + threadIdx.x;   // grid sized exactly E/256
    atomicAdd(&g_cnt[row[e]], 1);
}

__global__ void inv_kernel() {
    int v = blockIdx.x * 256 + threadIdx.x;
    if (v < NNODE) g_inv[v] = 1.f / fmaxf((float)g_cnt[v], 1.f);
}

// ---------------- fused edge-conv kernel ----------------
// One thread per edge, 256 edges per block.
// h = [ x[row] | x[col] | ef0 | ef1 | ef2 ]  (CIN total)
// hidden = relu(h@w1+b1); out = hidden@w2+b2
// scatter raw out to nsum[row]; store lrelu(out) (optionally after fused 3-layer MLP) to eout.
template <int CIN, bool FUSE_MLP>
__global__ __launch_bounds__(256)
void conv_kernel(const float* __restrict__ xn,
                 const float* __restrict__ ef0,
                 const float* __restrict__ ef1,
                 const float* __restrict__ ef2,
                 const int* __restrict__ ridx,
                 const int* __restrict__ cidx,
                 const float* __restrict__ w1, const float* __restrict__ b1,
                 const float* __restrict__ w2, const float* __restrict__ b2,
                 const float* __restrict__ mw1, const float* __restrict__ mb1,
                 const float* __restrict__ mw2, const float* __restrict__ mb2,
                 const float* __restrict__ mw3, const float* __restrict__ mb3,
                 float* __restrict__ nsum,
                 float* __restrict__ eout) {
    constexpr int NB = CIN / 32;
    constexpr int SP = 257;                // transpose buffer stride (odd -> conflict-free)
    extern __shared__ float sm[];
    float* cs  = sm;                       // 32 * 257 floats
    float* w1s = sm + 32 * SP;             // CIN * 32
    float* w2s = w1s + CIN * 32;           // 1024
    float* b1s = w2s + 1024;               // 32
    float* b2s = b1s + 32;                 // 32
    float* ms  = b2s + 32;                 // FUSE_MLP: mw1|mb1|mw2|mb2|mw3|mb3

    const int tid = threadIdx.x;
    const size_t tile0 = (size_t)blockIdx.x * 256;

    // stage weights
    for (int v = tid; v < CIN * 32; v += 256) w1s[v] = w1[v];
    for (int v = tid; v < 1024; v += 256)     w2s[v] = w2[v];
    if (tid < 32) { b1s[tid] = b1[tid]; b2s[tid] = b2[tid]; }
    if constexpr (FUSE_MLP) {
        for (int v = tid; v < 1024; v += 256) {
            ms[v] = mw1[v]; ms[1056 + v] = mw2[v]; ms[2112 + v] = mw3[v];
        }
        if (tid < 32) { ms[1024 + tid] = mb1[tid]; ms[2080 + tid] = mb2[tid]; ms[3136 + tid] = mb3[tid]; }
    }
    __syncthreads();

    const int e = (int)(tile0 + tid);
    const int r = ridx[e];
    const int c = cidx[e];

    float acc[32];
#pragma unroll
    for (int j = 0; j < 32; j++) acc[j] = b1s[j];

    const float* efp[3] = { ef0, ef1, ef2 };

    for (int b = 0; b < NB; b++) {
        if (b < 2) {
            // gather node features straight from L2 (x is only 6.4 MB)
            const float* src = xn + (size_t)(b == 0 ? r : c) * 32;
#pragma unroll
            for (int i4 = 0; i4 < 8; i4++) {
                float4 h4 = *(const float4*)(src + i4 * 4);
                float hv[4] = { h4.x, h4.y, h4.z, h4.w };
#pragma unroll
                for (int q = 0; q < 4; q++)
                    fma32(acc, hv[q], &w1s[(b * 32 + i4 * 4 + q) * 32]);
            }
        } else {
            // coalesced stage of 256x32 edge-feature chunk through shared transpose
            __syncthreads();
            const float* src = efp[b - 2] + tile0 * 32;
            for (int v = tid; v < 256 * 32; v += 256)
                cs[(v & 31) * SP + (v >> 5)] = src[v];
            __syncthreads();
#pragma unroll
            for (int i = 0; i < 32; i++) {
                float hv = cs[i * SP + tid];
                fma32(acc, hv, &w1s[(b * 32 + i) * 32]);
            }
        }
    }

    // second linear
    float out[32];
#pragma unroll
    for (int j = 0; j < 32; j++) out[j] = b2s[j];
#pragma unroll
    for (int k = 0; k < 32; k++) {
        float hk = fmaxf(acc[k], 0.f);
        fma32(out, hk, &w2s[k * 32]);
    }

    // scatter raw edge output to node sums (vectorized L2 reductions)
    {
        float* np = nsum + (size_t)r * 32;
#pragma unroll
        for (int j4 = 0; j4 < 8; j4++) {
            asm volatile("red.global.add.v4.f32 [%0], {%1,%2,%3,%4};"
                         :: "l"(np + j4 * 4),
                            "f"(out[j4 * 4 + 0]), "f"(out[j4 * 4 + 1]),
                            "f"(out[j4 * 4 + 2]), "f"(out[j4 * 4 + 3])
                         : "memory");
        }
    }

    // lrelu for the edge path
#pragma unroll
    for (int j = 0; j < 32; j++) out[j] = lrelu(out[j]);

    if constexpr (FUSE_MLP) {
        const float* mw1s = ms;        const float* mb1s = ms + 1024;
        const float* mw2s = ms + 1056; const float* mb2s = ms + 2080;
        const float* mw3s = ms + 2112; const float* mb3s = ms + 3136;
        float t[32], u[32];
#pragma unroll
        for (int j = 0; j < 32; j++) t[j] = mb1s[j];
#pragma unroll
        for (int k = 0; k < 32; k++) fma32(t, out[k], mw1s + k * 32);
#pragma unroll
        for (int j = 0; j < 32; j++) t[j] = lrelu(t[j]);
#pragma unroll
        for (int j = 0; j < 32; j++) u[j] = mb2s[j];
#pragma unroll
        for (int k = 0; k < 32; k++) fma32(u, t[k], mw2s + k * 32);
#pragma unroll
        for (int j = 0; j < 32; j++) u[j] = lrelu(u[j]);
#pragma unroll
        for (int j = 0; j < 32; j++) t[j] = mb3s[j];
#pragma unroll
        for (int k = 0; k < 32; k++) fma32(t, u[k], mw3s + k * 32);
#pragma unroll
        for (int j = 0; j < 32; j++) out[j] = t[j];   // final (no lrelu)
    }

    // coalesced store via shared transpose
    __syncthreads();
#pragma unroll
    for (int j = 0; j < 32; j++) cs[j * SP + tid] = out[j];
    __syncthreads();
    float* dst = eout + tile0 * 32;
    for (int v = tid; v < 256 * 32; v += 256)
        dst[v] = cs[(v & 31) * SP + (v >> 5)];
}

// ---------------- node-side kernels ----------------
__global__ void node_lr_kernel(const float* __restrict__ ns, float* __restrict__ nout) {
    int idx = blockIdx.x * 256 + threadIdx.x;     // grid sized exactly N*32/256
    float v = ns[idx] * g_inv[idx >> 5];
    nout[idx] = lrelu(v);
}

__global__ __launch_bounds__(256)
void node_final_kernel(const float* __restrict__ ns,
                       const float* __restrict__ nw1, const float* __restrict__ nb1,
                       const float* __restrict__ nw2, const float* __restrict__ nb2,
                       const float* __restrict__ nw3, const float* __restrict__ nb3,
                       float* __restrict__ out) {
    __shared__ float ws1[1024], ws2[1024], ws3[1024], bs1[32], bs2[32], bs3[32];
    int tid = threadIdx.x;
    for (int v = tid; v < 1024; v += 256) { ws1[v] = nw1[v]; ws2[v] = nw2[v]; ws3[v] = nw3[v]; }
    if (tid < 32) { bs1[tid] = nb1[tid]; bs2[tid] = nb2[tid]; bs3[tid] = nb3[tid]; }
    __syncthreads();

    int v = blockIdx.x * 256 + tid;
    if (v >= NNODE) return;

    float inv = g_inv[v];
    float x[32];
#pragma unroll
    for (int j4 = 0; j4 < 8; j4++) {
        float4 a = *(const float4*)(ns + (size_t)v * 32 + j4 * 4);
        x[j4 * 4 + 0] = lrelu(a.x * inv);
        x[j4 * 4 + 1] = lrelu(a.y * inv);
        x[j4 * 4 + 2] = lrelu(a.z * inv);
        x[j4 * 4 + 3] = lrelu(a.w * inv);
    }

    float t[32], u[32];
#pragma unroll
    for (int j = 0; j < 32; j++) t[j] = bs1[j];
#pragma unroll
    for (int k = 0; k < 32; k++) fma32(t, x[k], ws1 + k * 32);
#pragma unroll
    for (int j = 0; j < 32; j++) t[j] = lrelu(t[j]);
#pragma unroll
    for (int j = 0; j < 32; j++) u[j] = bs2[j];
#pragma unroll
    for (int k = 0; k < 32; k++) fma32(u, t[k], ws2 + k * 32);
#pragma unroll
    for (int j = 0; j < 32; j++) u[j] = lrelu(u[j]);
#pragma unroll
    for (int j = 0; j < 32; j++) t[j] = bs3[j];
#pragma unroll
    for (int k = 0; k < 32; k++) fma32(t, u[k], ws3 + k * 32);

    float* dst = out + (size_t)v * 32;
#pragma unroll
    for (int j4 = 0; j4 < 8; j4++) {
        float4 a = make_float4(t[j4 * 4 + 0], t[j4 * 4 + 1], t[j4 * 4 + 2], t[j4 * 4 + 3]);
        *(float4*)(dst + j4 * 4) = a;
    }
}

// ---------------- launch ----------------
extern "C" void kernel_launch(void* const* d_in, const int* in_sizes, int n_in,
                              void* d_out, int out_size) {
    const float* node_attr = (const float*)d_in[0];
    const float* edge_attr = (const float*)d_in[1];
    const int*   edge_index = (const int*)d_in[2];
    const float* c1w1 = (const float*)d_in[3];  const float* c1b1 = (const float*)d_in[4];
    const float* c1w2 = (const float*)d_in[5];  const float* c1b2 = (const float*)d_in[6];
    const float* c2w1 = (const float*)d_in[7];  const float* c2b1 = (const float*)d_in[8];
    const float* c2w2 = (const float*)d_in[9];  const float* c2b2 = (const float*)d_in[10];
    const float* c3w1 = (const float*)d_in[11]; const float* c3b1 = (const float*)d_in[12];
    const float* c3w2 = (const float*)d_in[13]; const float* c3b2 = (const float*)d_in[14];
    const float* nw1 = (const float*)d_in[15];  const float* nb1 = (const float*)d_in[16];
    const float* nw2 = (const float*)d_in[17];  const float* nb2 = (const float*)d_in[18];
    const float* nw3 = (const float*)d_in[19];  const float* nb3 = (const float*)d_in[20];
    const float* ew1 = (const float*)d_in[21];  const float* eb1 = (const float*)d_in[22];
    const float* ew2 = (const float*)d_in[23];  const float* eb2 = (const float*)d_in[24];
    const float* ew3 = (const float*)d_in[25];  const float* eb3 = (const float*)d_in[26];

    float* out_node = (float*)d_out;
    float* out_edge = out_node + (size_t)NNODE * 32;

    const int* row = edge_index;
    const int* col = edge_index + NEDGE;

    float *e1, *e2, *n1, *n2, *ns1, *ns2, *ns3;
    cudaGetSymbolAddress((void**)&e1, g_e1);
    cudaGetSymbolAddress((void**)&e2, g_e2);
    cudaGetSymbolAddress((void**)&n1, g_n1);
    cudaGetSymbolAddress((void**)&n2, g_n2);
    cudaGetSymbolAddress((void**)&ns1, g_ns1);
    cudaGetSymbolAddress((void**)&ns2, g_ns2);
    cudaGetSymbolAddress((void**)&ns3, g_ns3);

    // dynamic smem sizes (bytes)
    const int SM1 = (32 * 257 + 96 * 32 + 1024 + 64) * 4;            // 49536
    const int SM2 = (32 * 257 + 128 * 32 + 1024 + 64) * 4;           // 53632
    const int SM3 = (32 * 257 + 160 * 32 + 1024 + 64 + 3168) * 4;    // 70400
    cudaFuncSetAttribute(conv_kernel<96, false>,  cudaFuncAttributeMaxDynamicSharedMemorySize, SM1);
    cudaFuncSetAttribute(conv_kernel<128, false>, cudaFuncAttributeMaxDynamicSharedMemorySize, SM2);
    cudaFuncSetAttribute(conv_kernel<160, true>,  cudaFuncAttributeMaxDynamicSharedMemorySize, SM3);

    const int EB = NEDGE / 256;           // 6250
    const int NB32 = NNODE * 32 / 256;    // 6250

    zero_kernel<<<1024, 256>>>();
    count_kernel<<<EB, 256>>>(row);
    inv_kernel<<<(NNODE + 255) / 256, 256>>>();

    conv_kernel<96, false><<<EB, 256, SM1>>>(
        node_attr, edge_attr, nullptr, nullptr, row, col,
        c1w1, c1b1, c1w2, c1b2,
        nullptr, nullptr, nullptr, nullptr, nullptr, nullptr,
        ns1, e1);
    node_lr_kernel<<<NB32, 256>>>(ns1, n1);

    conv_kernel<128, false><<<EB, 256, SM2>>>(
        n1, e1, edge_attr, nullptr, row, col,
        c2w1, c2b1, c2w2, c2b2,
        nullptr, nullptr, nullptr, nullptr, nullptr, nullptr,
        ns2, e2);
    node_lr_kernel<<<NB32, 256>>>(ns2, n2);

    conv_kernel<160, true><<<EB, 256, SM3>>>(
        n2, e2, e1, edge_attr, row, col,
        c3w1, c3b1, c3w2, c3b2,
        ew1, eb1, ew2, eb2, ew3, eb3,
        ns3, out_edge);

    node_final_kernel<<<(NNODE + 255) / 256, 256>>>(
        ns3, nw1, nb1, nw2, nb2, nw3, nb3, out_node);
}

// round 4
// speedup vs baseline: 1.4384x; 1.4384x over previous
#include <cuda_runtime.h>
#include <cstdint>

#define NNODE 50000
#define NEDGE 1600000

typedef unsigned long long ull;

// ---------------- device scratch (no allocations allowed) ----------------
__device__ float g_e1[(size_t)NEDGE * 32];   // lrelu(e1)
__device__ float g_e2[(size_t)NEDGE * 32];   // lrelu(e2)
__device__ float g_n1[(size_t)NNODE * 32];
__device__ float g_n2[(size_t)NNODE * 32];
__device__ float g_ns1[(size_t)NNODE * 32];
__device__ float g_ns2[(size_t)NNODE * 32];
__device__ float g_ns3[(size_t)NNODE * 32];
__device__ float g_inv[NNODE];
__device__ int   g_cnt[NNODE];

__device__ __forceinline__ float lrelu(float x) { return x > 0.f ? x : 0.2f * x; }

__device__ __forceinline__ ull bcast2(float v) {
    ull r; unsigned u = __float_as_uint(v);
    asm("mov.b64 %0, {%1,%1};" : "=l"(r) : "r"(u));
    return r;
}
__device__ __forceinline__ void unpack2(ull v, float& a, float& b) {
    unsigned lo, hi;
    asm("mov.b64 {%0,%1}, %2;" : "=r"(lo), "=r"(hi) : "l"(v));
    a = __uint_as_float(lo); b = __uint_as_float(hi);
}
// acc[16] packed f32x2 accumulators += hv * wrow[0..31]
__device__ __forceinline__ void fma16p(ull (&acc)[16], ull h2, const float* __restrict__ wrow) {
    const ulonglong2* w = (const ulonglong2*)wrow;
#pragma unroll
    for (int j = 0; j < 8; j++) {
        ulonglong2 wv = w[j];
        asm("fma.rn.f32x2 %0, %1, %2, %0;" : "+l"(acc[2 * j + 0]) : "l"(h2), "l"(wv.x));
        asm("fma.rn.f32x2 %0, %1, %2, %0;" : "+l"(acc[2 * j + 1]) : "l"(h2), "l"(wv.y));
    }
}

// ---------------- setup kernels ----------------
__global__ void zero_kernel() {
    int stride = gridDim.x * blockDim.x;
    int i0 = blockIdx.x * blockDim.x + threadIdx.x;
    for (int v = i0; v < NNODE * 32; v += stride) {
        g_ns1[v] = 0.f; g_ns2[v] = 0.f; g_ns3[v] = 0.f;
    }
    for (int v = i0; v < NNODE; v += stride) g_cnt[v] = 0;
}

__global__ void count_kernel(const int* __restrict__ row) {
    int e = blockIdx.x * 256 + threadIdx.x;
    atomicAdd(&g_cnt[row[e]], 1);
}

__global__ void inv_kernel() {
    int v = blockIdx.x * 256 + threadIdx.x;
    if (v < NNODE) g_inv[v] = 1.f / fmaxf((float)g_cnt[v], 1.f);
}

// ---------------- fused edge-conv kernel ----------------
// One thread per edge, 256 edges/block. All inputs staged through a shared
// transpose buffer (coalesced GMEM access both for edge features and node
// gathers). GEMM accumulation in packed f32x2.
template <int CIN, bool FUSE_MLP>
__global__ __launch_bounds__(256, 3)
void conv_kernel(const float* __restrict__ xn,
                 const float* __restrict__ ef0,
                 const float* __restrict__ ef1,
                 const float* __restrict__ ef2,
                 const int* __restrict__ ridx,
                 const int* __restrict__ cidx,
                 const float* __restrict__ w1, const float* __restrict__ b1,
                 const float* __restrict__ w2, const float* __restrict__ b2,
                 const float* __restrict__ mw1, const float* __restrict__ mb1,
                 const float* __restrict__ mw2, const float* __restrict__ mb2,
                 const float* __restrict__ mw3, const float* __restrict__ mb3,
                 float* __restrict__ nsum,
                 float* __restrict__ eout) {
    constexpr int NB = CIN / 32;
    constexpr int SP = 257;                // conflict-free transpose stride
    constexpr int MSZ = FUSE_MLP ? 3168 : 0;
    extern __shared__ float sm[];
    float* cs  = sm;                       // 32 * 257
    float* w1s = sm + 32 * SP;             // CIN*32 (16B aligned)
    float* w2s = w1s + CIN * 32;           // 1024
    float* b1s = w2s + 1024;               // 32 (8B aligned)
    float* b2s = b1s + 32;                 // 32
    float* ms  = b2s + 32;                 // fused MLP weights
    int*   rs  = (int*)(ms + MSZ);         // 256
    int*   cls = rs + 256;                 // 256

    const int tid = threadIdx.x;
    const size_t tile0 = (size_t)blockIdx.x * 256;
    const int e = (int)(tile0 + tid);

    // stage weights + this block's indices
    for (int v = tid; v < CIN * 32; v += 256) w1s[v] = w1[v];
    for (int v = tid; v < 1024; v += 256)     w2s[v] = w2[v];
    if (tid < 32) { b1s[tid] = b1[tid]; b2s[tid] = b2[tid]; }
    if constexpr (FUSE_MLP) {
        for (int v = tid; v < 1024; v += 256) {
            ms[v] = mw1[v]; ms[1056 + v] = mw2[v]; ms[2112 + v] = mw3[v];
        }
        if (tid < 32) { ms[1024 + tid] = mb1[tid]; ms[2080 + tid] = mb2[tid]; ms[3136 + tid] = mb3[tid]; }
    }
    const int r = ridx[e];
    rs[tid] = r;
    cls[tid] = cidx[e];
    __syncthreads();

    ull acc[16];
    {
        const ull* bp = (const ull*)b1s;
#pragma unroll
        for (int j = 0; j < 16; j++) acc[j] = bp[j];
    }

    const float* efp[3] = { ef0, ef1, ef2 };

    for (int b = 0; b < NB; b++) {
        __syncthreads();
        if (b < 2) {
            // warp-coalesced gather: one 128B node row per warp-iteration
            const int* sidx = (b == 0) ? rs : cls;
            const int ch = tid & 31;
            const int e0 = tid >> 5;
#pragma unroll
            for (int it = 0; it < 32; it++) {
                int eidx = e0 + it * 8;
                cs[ch * SP + eidx] = xn[(size_t)sidx[eidx] * 32 + ch];
            }
        } else {
            // coalesced vector stage of 256x32 edge-feature chunk
            const float4* src = (const float4*)(efp[b - 2] + tile0 * 32);
#pragma unroll
            for (int it = 0; it < 8; it++) {
                int v = tid + it * 256;
                float4 f = src[v];
                int m = 4 * v;
                int eidx = m >> 5;
                int ch = m & 31;
                cs[(ch + 0) * SP + eidx] = f.x;
                cs[(ch + 1) * SP + eidx] = f.y;
                cs[(ch + 2) * SP + eidx] = f.z;
                cs[(ch + 3) * SP + eidx] = f.w;
            }
        }
        __syncthreads();
#pragma unroll
        for (int i = 0; i < 32; i++) {
            ull h2 = bcast2(cs[i * SP + tid]);
            fma16p(acc, h2, &w1s[(b * 32 + i) * 32]);
        }
    }

    // stage relu(hidden) into this thread's private shared column (no sync needed)
#pragma unroll
    for (int j = 0; j < 16; j++) {
        float a0, a1; unpack2(acc[j], a0, a1);
        cs[(2 * j + 0) * SP + tid] = fmaxf(a0, 0.f);
        cs[(2 * j + 1) * SP + tid] = fmaxf(a1, 0.f);
    }

    // second linear
    ull out2[16];
    {
        const ull* bp = (const ull*)b2s;
#pragma unroll
        for (int j = 0; j < 16; j++) out2[j] = bp[j];
    }
#pragma unroll
    for (int k = 0; k < 32; k++) {
        ull h2 = bcast2(cs[k * SP + tid]);
        fma16p(out2, h2, &w2s[k * 32]);
    }

    float o[32];
#pragma unroll
    for (int j = 0; j < 16; j++) unpack2(out2[j], o[2 * j], o[2 * j + 1]);

    // scatter raw edge output to node sums (vectorized L2 reductions)
    {
        float* np = nsum + (size_t)r * 32;
#pragma unroll
        for (int j4 = 0; j4 < 8; j4++) {
            asm volatile("red.global.add.v4.f32 [%0], {%1,%2,%3,%4};"
                         :: "l"(np + j4 * 4),
                            "f"(o[j4 * 4 + 0]), "f"(o[j4 * 4 + 1]),
                            "f"(o[j4 * 4 + 2]), "f"(o[j4 * 4 + 3])
                         : "memory");
        }
    }

#pragma unroll
    for (int j = 0; j < 32; j++) o[j] = lrelu(o[j]);

    if constexpr (FUSE_MLP) {
        // write current edge value to private column, run 3 fused 32x32 layers
#pragma unroll
        for (int j = 0; j < 32; j++) cs[j * SP + tid] = o[j];
        const float* mws[3] = { ms, ms + 1056, ms + 2112 };
        const float* mbs[3] = { ms + 1024, ms + 2080, ms + 3136 };
#pragma unroll
        for (int L = 0; L < 3; L++) {
            ull t2[16];
            const ull* bp = (const ull*)mbs[L];
#pragma unroll
            for (int j = 0; j < 16; j++) t2[j] = bp[j];
#pragma unroll
            for (int k = 0; k < 32; k++) {
                ull h2 = bcast2(cs[k * SP + tid]);
                fma16p(t2, h2, mws[L] + k * 32);
            }
#pragma unroll
            for (int j = 0; j < 16; j++) {
                float a0, a1; unpack2(t2[j], a0, a1);
                if (L < 2) { a0 = lrelu(a0); a1 = lrelu(a1); }
                cs[(2 * j + 0) * SP + tid] = a0;
                cs[(2 * j + 1) * SP + tid] = a1;
            }
        }
    } else {
#pragma unroll
        for (int j = 0; j < 32; j++) cs[j * SP + tid] = o[j];
    }

    // coalesced vectorized store from transpose buffer
    __syncthreads();
    float4* dst = (float4*)(eout + tile0 * 32);
#pragma unroll
    for (int it = 0; it < 8; it++) {
        int v = tid + it * 256;
        int m = 4 * v;
        int eidx = m >> 5;
        int ch = m & 31;
        float4 f;
        f.x = cs[(ch + 0) * SP + eidx];
        f.y = cs[(ch + 1) * SP + eidx];
        f.z = cs[(ch + 2) * SP + eidx];
        f.w = cs[(ch + 3) * SP + eidx];
        dst[v] = f;
    }
}

// ---------------- node-side kernels ----------------
__global__ void node_lr_kernel(const float* __restrict__ ns, float* __restrict__ nout) {
    int idx = blockIdx.x * 256 + threadIdx.x;     // grid sized exactly N*32/256
    float v = ns[idx] * g_inv[idx >> 5];
    nout[idx] = lrelu(v);
}

__global__ __launch_bounds__(256)
void node_final_kernel(const float* __restrict__ ns,
                       const float* __restrict__ nw1, const float* __restrict__ nb1,
                       const float* __restrict__ nw2, const float* __restrict__ nb2,
                       const float* __restrict__ nw3, const float* __restrict__ nb3,
                       float* __restrict__ out) {
    __shared__ float ws1[1024], ws2[1024], ws3[1024], bs1[32], bs2[32], bs3[32];
    int tid = threadIdx.x;
    for (int v = tid; v < 1024; v += 256) { ws1[v] = nw1[v]; ws2[v] = nw2[v]; ws3[v] = nw3[v]; }
    if (tid < 32) { bs1[tid] = nb1[tid]; bs2[tid] = nb2[tid]; bs3[tid] = nb3[tid]; }
    __syncthreads();

    int v = blockIdx.x * 256 + tid;
    if (v >= NNODE) return;

    float inv = g_inv[v];
    float x[32];
#pragma unroll
    for (int j4 = 0; j4 < 8; j4++) {
        float4 a = *(const float4*)(ns + (size_t)v * 32 + j4 * 4);
        x[j4 * 4 + 0] = lrelu(a.x * inv);
        x[j4 * 4 + 1] = lrelu(a.y * inv);
        x[j4 * 4 + 2] = lrelu(a.z * inv);
        x[j4 * 4 + 3] = lrelu(a.w * inv);
    }

    ull t2[16], u2[16];
    {
        const ull* bp = (const ull*)bs1;
#pragma unroll
        for (int j = 0; j < 16; j++) t2[j] = bp[j];
    }
#pragma unroll
    for (int k = 0; k < 32; k++) fma16p(t2, bcast2(x[k]), ws1 + k * 32);
#pragma unroll
    for (int j = 0; j < 16; j++) { float a0, a1; unpack2(t2[j], a0, a1); x[2 * j] = lrelu(a0); x[2 * j + 1] = lrelu(a1); }
    {
        const ull* bp = (const ull*)bs2;
#pragma unroll
        for (int j = 0; j < 16; j++) u2[j] = bp[j];
    }
#pragma unroll
    for (int k = 0; k < 32; k++) fma16p(u2, bcast2(x[k]), ws2 + k * 32);
#pragma unroll
    for (int j = 0; j < 16; j++) { float a0, a1; unpack2(u2[j], a0, a1); x[2 * j] = lrelu(a0); x[2 * j + 1] = lrelu(a1); }
    {
        const ull* bp = (const ull*)bs3;
#pragma unroll
        for (int j = 0; j < 16; j++) t2[j] = bp[j];
    }
#pragma unroll
    for (int k = 0; k < 32; k++) fma16p(t2, bcast2(x[k]), ws3 + k * 32);
#pragma unroll
    for (int j = 0; j < 16; j++) unpack2(t2[j], x[2 * j], x[2 * j + 1]);

    float* dst = out + (size_t)v * 32;
#pragma unroll
    for (int j4 = 0; j4 < 8; j4++) {
        float4 a = make_float4(x[j4 * 4 + 0], x[j4 * 4 + 1], x[j4 * 4 + 2], x[j4 * 4 + 3]);
        *(float4*)(dst + j4 * 4) = a;
    }
}

// ---------------- launch ----------------
extern "C" void kernel_launch(void* const* d_in, const int* in_sizes, int n_in,
                              void* d_out, int out_size) {
    const float* node_attr = (const float*)d_in[0];
    const float* edge_attr = (const float*)d_in[1];
    const int*   edge_index = (const int*)d_in[2];
    const float* c1w1 = (const float*)d_in[3];  const float* c1b1 = (const float*)d_in[4];
    const float* c1w2 = (const float*)d_in[5];  const float* c1b2 = (const float*)d_in[6];
    const float* c2w1 = (const float*)d_in[7];  const float* c2b1 = (const float*)d_in[8];
    const float* c2w2 = (const float*)d_in[9];  const float* c2b2 = (const float*)d_in[10];
    const float* c3w1 = (const float*)d_in[11]; const float* c3b1 = (const float*)d_in[12];
    const float* c3w2 = (const float*)d_in[13]; const float* c3b2 = (const float*)d_in[14];
    const float* nw1 = (const float*)d_in[15];  const float* nb1 = (const float*)d_in[16];
    const float* nw2 = (const float*)d_in[17];  const float* nb2 = (const float*)d_in[18];
    const float* nw3 = (const float*)d_in[19];  const float* nb3 = (const float*)d_in[20];
    const float* ew1 = (const float*)d_in[21];  const float* eb1 = (const float*)d_in[22];
    const float* ew2 = (const float*)d_in[23];  const float* eb2 = (const float*)d_in[24];
    const float* ew3 = (const float*)d_in[25];  const float* eb3 = (const float*)d_in[26];

    float* out_node = (float*)d_out;
    float* out_edge = out_node + (size_t)NNODE * 32;

    const int* row = edge_index;
    const int* col = edge_index + NEDGE;

    float *e1, *e2, *n1, *n2, *ns1, *ns2, *ns3;
    cudaGetSymbolAddress((void**)&e1, g_e1);
    cudaGetSymbolAddress((void**)&e2, g_e2);
    cudaGetSymbolAddress((void**)&n1, g_n1);
    cudaGetSymbolAddress((void**)&n2, g_n2);
    cudaGetSymbolAddress((void**)&ns1, g_ns1);
    cudaGetSymbolAddress((void**)&ns2, g_ns2);
    cudaGetSymbolAddress((void**)&ns3, g_ns3);

    // dynamic smem (floats): cs 8224 | w1 CIN*32 | w2 1024 | b 64 | [ms 3168] | idx 512
    const int SM1 = (8224 + 96 * 32 + 1024 + 64 + 512) * 4;             // 51584
    const int SM2 = (8224 + 128 * 32 + 1024 + 64 + 512) * 4;            // 55680
    const int SM3 = (8224 + 160 * 32 + 1024 + 64 + 3168 + 512) * 4;     // 72448
    cudaFuncSetAttribute(conv_kernel<96, false>,  cudaFuncAttributeMaxDynamicSharedMemorySize, SM1);
    cudaFuncSetAttribute(conv_kernel<128, false>, cudaFuncAttributeMaxDynamicSharedMemorySize, SM2);
    cudaFuncSetAttribute(conv_kernel<160, true>,  cudaFuncAttributeMaxDynamicSharedMemorySize, SM3);

    const int EB = NEDGE / 256;           // 6250
    const int NB32 = NNODE * 32 / 256;    // 6250

    zero_kernel<<<1024, 256>>>();
    count_kernel<<<EB, 256>>>(row);
    inv_kernel<<<(NNODE + 255) / 256, 256>>>();

    conv_kernel<96, false><<<EB, 256, SM1>>>(
        node_attr, edge_attr, nullptr, nullptr, row, col,
        c1w1, c1b1, c1w2, c1b2,
        nullptr, nullptr, nullptr, nullptr, nullptr, nullptr,
        ns1, e1);
    node_lr_kernel<<<NB32, 256>>>(ns1, n1);

    conv_kernel<128, false><<<EB, 256, SM2>>>(
        n1, e1, edge_attr, nullptr, row, col,
        c2w1, c2b1, c2w2, c2b2,
        nullptr, nullptr, nullptr, nullptr, nullptr, nullptr,
        ns2, e2);
    node_lr_kernel<<<NB32, 256>>>(ns2, n2);

    conv_kernel<160, true><<<EB, 256, SM3>>>(
        n2, e2, e1, edge_attr, row, col,
        c3w1, c3b1, c3w2, c3b2,
        ew1, eb1, ew2, eb2, ew3, eb3,
        ns3, out_edge);

    node_final_kernel<<<(NNODE + 255) / 256, 256>>>(
        ns3, nw1, nb1, nw2, nb2, nw3, nb3, out_node);
}

// round 5
// speedup vs baseline: 1.4386x; 1.0001x over previous
#include <cuda_runtime.h>
#include <cstdint>

#define NNODE 50000
#define NEDGE 1600000

typedef unsigned long long ull;

// ---------------- device scratch (no allocations allowed) ----------------
__device__ float g_e1[(size_t)NEDGE * 32];   // lrelu(e1)
__device__ float g_e2[(size_t)NEDGE * 32];   // lrelu(e2)
__device__ float g_n1[(size_t)NNODE * 32];
__device__ float g_n2[(size_t)NNODE * 32];
__device__ float g_ns1[(size_t)NNODE * 32];
__device__ float g_ns2[(size_t)NNODE * 32];
__device__ float g_ns3[(size_t)NNODE * 32];
__device__ float g_inv[NNODE];
__device__ int   g_cnt[NNODE];

__device__ __forceinline__ float lrelu(float x) { return x > 0.f ? x : 0.2f * x; }

__device__ __forceinline__ ull bcast2(float v) {
    ull r; unsigned u = __float_as_uint(v);
    asm("mov.b64 %0, {%1,%1};" : "=l"(r) : "r"(u));
    return r;
}
__device__ __forceinline__ void unpack2(ull v, float& a, float& b) {
    unsigned lo, hi;
    asm("mov.b64 {%0,%1}, %2;" : "=r"(lo), "=r"(hi) : "l"(v));
    a = __uint_as_float(lo); b = __uint_as_float(hi);
}
// acc[16] packed f32x2 accumulators += hv * wrow[0..31]
__device__ __forceinline__ void fma16p(ull (&acc)[16], ull h2, const float* __restrict__ wrow) {
    const ulonglong2* w = (const ulonglong2*)wrow;
#pragma unroll
    for (int j = 0; j < 8; j++) {
        ulonglong2 wv = w[j];
        asm("fma.rn.f32x2 %0, %1, %2, %0;" : "+l"(acc[2 * j + 0]) : "l"(h2), "l"(wv.x));
        asm("fma.rn.f32x2 %0, %1, %2, %0;" : "+l"(acc[2 * j + 1]) : "l"(h2), "l"(wv.y));
    }
}

// ---------------- setup kernels ----------------
__global__ void zero_kernel() {
    int stride = gridDim.x * blockDim.x;
    int i0 = blockIdx.x * blockDim.x + threadIdx.x;
    for (int v = i0; v < NNODE * 32; v += stride) {
        g_ns1[v] = 0.f; g_ns2[v] = 0.f; g_ns3[v] = 0.f;
    }
    for (int v = i0; v < NNODE; v += stride) g_cnt[v] = 0;
}

__global__ void count_kernel(const int* __restrict__ row) {
    int e = blockIdx.x * 256 + threadIdx.x;
    atomicAdd(&g_cnt[row[e]], 1);
}

__global__ void inv_kernel() {
    int v = blockIdx.x * 256 + threadIdx.x;
    if (v < NNODE) g_inv[v] = 1.f / fmaxf((float)g_cnt[v], 1.f);
}

// ---------------- fused edge-conv kernel ----------------
// One thread per edge, 256 edges/block. All inputs staged through a shared
// transpose buffer (coalesced GMEM access both for edge features and node
// gathers). GEMM accumulation in packed f32x2.
template <int CIN, bool FUSE_MLP>
__global__ __launch_bounds__(256, 3)
void conv_kernel(const float* __restrict__ xn,
                 const float* __restrict__ ef0,
                 const float* __restrict__ ef1,
                 const float* __restrict__ ef2,
                 const int* __restrict__ ridx,
                 const int* __restrict__ cidx,
                 const float* __restrict__ w1, const float* __restrict__ b1,
                 const float* __restrict__ w2, const float* __restrict__ b2,
                 const float* __restrict__ mw1, const float* __restrict__ mb1,
                 const float* __restrict__ mw2, const float* __restrict__ mb2,
                 const float* __restrict__ mw3, const float* __restrict__ mb3,
                 float* __restrict__ nsum,
                 float* __restrict__ eout) {
    constexpr int NB = CIN / 32;
    constexpr int SP = 257;                // conflict-free transpose stride
    constexpr int MSZ = FUSE_MLP ? 3168 : 0;
    extern __shared__ float sm[];
    float* cs  = sm;                       // 32 * 257
    float* w1s = sm + 32 * SP;             // CIN*32 (16B aligned)
    float* w2s = w1s + CIN * 32;           // 1024
    float* b1s = w2s + 1024;               // 32 (8B aligned)
    float* b2s = b1s + 32;                 // 32
    float* ms  = b2s + 32;                 // fused MLP weights
    int*   rs  = (int*)(ms + MSZ);         // 256
    int*   cls = rs + 256;                 // 256

    const int tid = threadIdx.x;
    const size_t tile0 = (size_t)blockIdx.x * 256;
    const int e = (int)(tile0 + tid);

    // stage weights + this block's indices
    for (int v = tid; v < CIN * 32; v += 256) w1s[v] = w1[v];
    for (int v = tid; v < 1024; v += 256)     w2s[v] = w2[v];
    if (tid < 32) { b1s[tid] = b1[tid]; b2s[tid] = b2[tid]; }
    if constexpr (FUSE_MLP) {
        for (int v = tid; v < 1024; v += 256) {
            ms[v] = mw1[v]; ms[1056 + v] = mw2[v]; ms[2112 + v] = mw3[v];
        }
        if (tid < 32) { ms[1024 + tid] = mb1[tid]; ms[2080 + tid] = mb2[tid]; ms[3136 + tid] = mb3[tid]; }
    }
    const int r = ridx[e];
    rs[tid] = r;
    cls[tid] = cidx[e];
    __syncthreads();

    ull acc[16];
    {
        const ull* bp = (const ull*)b1s;
#pragma unroll
        for (int j = 0; j < 16; j++) acc[j] = bp[j];
    }

    const float* efp[3] = { ef0, ef1, ef2 };

    for (int b = 0; b < NB; b++) {
        __syncthreads();
        if (b < 2) {
            // warp-coalesced gather: one 128B node row per warp-iteration
            const int* sidx = (b == 0) ? rs : cls;
            const int ch = tid & 31;
            const int e0 = tid >> 5;
#pragma unroll
            for (int it = 0; it < 32; it++) {
                int eidx = e0 + it * 8;
                cs[ch * SP + eidx] = xn[(size_t)sidx[eidx] * 32 + ch];
            }
        } else {
            // coalesced vector stage of 256x32 edge-feature chunk
            const float4* src = (const float4*)(efp[b - 2] + tile0 * 32);
#pragma unroll
            for (int it = 0; it < 8; it++) {
                int v = tid + it * 256;
                float4 f = src[v];
                int m = 4 * v;
                int eidx = m >> 5;
                int ch = m & 31;
                cs[(ch + 0) * SP + eidx] = f.x;
                cs[(ch + 1) * SP + eidx] = f.y;
                cs[(ch + 2) * SP + eidx] = f.z;
                cs[(ch + 3) * SP + eidx] = f.w;
            }
        }
        __syncthreads();
#pragma unroll
        for (int i = 0; i < 32; i++) {
            ull h2 = bcast2(cs[i * SP + tid]);
            fma16p(acc, h2, &w1s[(b * 32 + i) * 32]);
        }
    }

    // stage relu(hidden) into this thread's private shared column (no sync needed)
#pragma unroll
    for (int j = 0; j < 16; j++) {
        float a0, a1; unpack2(acc[j], a0, a1);
        cs[(2 * j + 0) * SP + tid] = fmaxf(a0, 0.f);
        cs[(2 * j + 1) * SP + tid] = fmaxf(a1, 0.f);
    }

    // second linear
    ull out2[16];
    {
        const ull* bp = (const ull*)b2s;
#pragma unroll
        for (int j = 0; j < 16; j++) out2[j] = bp[j];
    }
#pragma unroll
    for (int k = 0; k < 32; k++) {
        ull h2 = bcast2(cs[k * SP + tid]);
        fma16p(out2, h2, &w2s[k * 32]);
    }

    float o[32];
#pragma unroll
    for (int j = 0; j < 16; j++) unpack2(out2[j], o[2 * j], o[2 * j + 1]);

    // scatter raw edge output to node sums (vectorized L2 reductions)
    {
        float* np = nsum + (size_t)r * 32;
#pragma unroll
        for (int j4 = 0; j4 < 8; j4++) {
            asm volatile("red.global.add.v4.f32 [%0], {%1,%2,%3,%4};"
                         :: "l"(np + j4 * 4),
                            "f"(o[j4 * 4 + 0]), "f"(o[j4 * 4 + 1]),
                            "f"(o[j4 * 4 + 2]), "f"(o[j4 * 4 + 3])
                         : "memory");
        }
    }

#pragma unroll
    for (int j = 0; j < 32; j++) o[j] = lrelu(o[j]);

    if constexpr (FUSE_MLP) {
        // write current edge value to private column, run 3 fused 32x32 layers
#pragma unroll
        for (int j = 0; j < 32; j++) cs[j * SP + tid] = o[j];
        const float* mws[3] = { ms, ms + 1056, ms + 2112 };
        const float* mbs[3] = { ms + 1024, ms + 2080, ms + 3136 };
#pragma unroll
        for (int L = 0; L < 3; L++) {
            ull t2[16];
            const ull* bp = (const ull*)mbs[L];
#pragma unroll
            for (int j = 0; j < 16; j++) t2[j] = bp[j];
#pragma unroll
            for (int k = 0; k < 32; k++) {
                ull h2 = bcast2(cs[k * SP + tid]);
                fma16p(t2, h2, mws[L] + k * 32);
            }
#pragma unroll
            for (int j = 0; j < 16; j++) {
                float a0, a1; unpack2(t2[j], a0, a1);
                if (L < 2) { a0 = lrelu(a0); a1 = lrelu(a1); }
                cs[(2 * j + 0) * SP + tid] = a0;
                cs[(2 * j + 1) * SP + tid] = a1;
            }
        }
    } else {
#pragma unroll
        for (int j = 0; j < 32; j++) cs[j * SP + tid] = o[j];
    }

    // coalesced vectorized store from transpose buffer
    __syncthreads();
    float4* dst = (float4*)(eout + tile0 * 32);
#pragma unroll
    for (int it = 0; it < 8; it++) {
        int v = tid + it * 256;
        int m = 4 * v;
        int eidx = m >> 5;
        int ch = m & 31;
        float4 f;
        f.x = cs[(ch + 0) * SP + eidx];
        f.y = cs[(ch + 1) * SP + eidx];
        f.z = cs[(ch + 2) * SP + eidx];
        f.w = cs[(ch + 3) * SP + eidx];
        dst[v] = f;
    }
}

// ---------------- node-side kernels ----------------
__global__ void node_lr_kernel(const float* __restrict__ ns, float* __restrict__ nout) {
    int idx = blockIdx.x * 256 + threadIdx.x;     // grid sized exactly N*32/256
    float v = ns[idx] * g_inv[idx >> 5];
    nout[idx] = lrelu(v);
}

__global__ __launch_bounds__(256)
void node_final_kernel(const float* __restrict__ ns,
                       const float* __restrict__ nw1, const float* __restrict__ nb1,
                       const float* __restrict__ nw2, const float* __restrict__ nb2,
                       const float* __restrict__ nw3, const float* __restrict__ nb3,
                       float* __restrict__ out) {
    __shared__ float ws1[1024], ws2[1024], ws3[1024], bs1[32], bs2[32], bs3[32];
    int tid = threadIdx.x;
    for (int v = tid; v < 1024; v += 256) { ws1[v] = nw1[v]; ws2[v] = nw2[v]; ws3[v] = nw3[v]; }
    if (tid < 32) { bs1[tid] = nb1[tid]; bs2[tid] = nb2[tid]; bs3[tid] = nb3[tid]; }
    __syncthreads();

    int v = blockIdx.x * 256 + tid;
    if (v >= NNODE) return;

    float inv = g_inv[v];
    float x[32];
#pragma unroll
    for (int j4 = 0; j4 < 8; j4++) {
        float4 a = *(const float4*)(ns + (size_t)v * 32 + j4 * 4);
        x[j4 * 4 + 0] = lrelu(a.x * inv);
        x[j4 * 4 + 1] = lrelu(a.y * inv);
        x[j4 * 4 + 2] = lrelu(a.z * inv);
        x[j4 * 4 + 3] = lrelu(a.w * inv);
    }

    ull t2[16], u2[16];
    {
        const ull* bp = (const ull*)bs1;
#pragma unroll
        for (int j = 0; j < 16; j++) t2[j] = bp[j];
    }
#pragma unroll
    for (int k = 0; k < 32; k++) fma16p(t2, bcast2(x[k]), ws1 + k * 32);
#pragma unroll
    for (int j = 0; j < 16; j++) { float a0, a1; unpack2(t2[j], a0, a1); x[2 * j] = lrelu(a0); x[2 * j + 1] = lrelu(a1); }
    {
        const ull* bp = (const ull*)bs2;
#pragma unroll
        for (int j = 0; j < 16; j++) u2[j] = bp[j];
    }
#pragma unroll
    for (int k = 0; k < 32; k++) fma16p(u2, bcast2(x[k]), ws2 + k * 32);
#pragma unroll
    for (int j = 0; j < 16; j++) { float a0, a1; unpack2(u2[j], a0, a1); x[2 * j] = lrelu(a0); x[2 * j + 1] = lrelu(a1); }
    {
        const ull* bp = (const ull*)bs3;
#pragma unroll
        for (int j = 0; j < 16; j++) t2[j] = bp[j];
    }
#pragma unroll
    for (int k = 0; k < 32; k++) fma16p(t2, bcast2(x[k]), ws3 + k * 32);
#pragma unroll
    for (int j = 0; j < 16; j++) unpack2(t2[j], x[2 * j], x[2 * j + 1]);

    float* dst = out + (size_t)v * 32;
#pragma unroll
    for (int j4 = 0; j4 < 8; j4++) {
        float4 a = make_float4(x[j4 * 4 + 0], x[j4 * 4 + 1], x[j4 * 4 + 2], x[j4 * 4 + 3]);
        *(float4*)(dst + j4 * 4) = a;
    }
}

// ---------------- launch ----------------
extern "C" void kernel_launch(void* const* d_in, const int* in_sizes, int n_in,
                              void* d_out, int out_size) {
    const float* node_attr = (const float*)d_in[0];
    const float* edge_attr = (const float*)d_in[1];
    const int*   edge_index = (const int*)d_in[2];
    const float* c1w1 = (const float*)d_in[3];  const float* c1b1 = (const float*)d_in[4];
    const float* c1w2 = (const float*)d_in[5];  const float* c1b2 = (const float*)d_in[6];
    const float* c2w1 = (const float*)d_in[7];  const float* c2b1 = (const float*)d_in[8];
    const float* c2w2 = (const float*)d_in[9];  const float* c2b2 = (const float*)d_in[10];
    const float* c3w1 = (const float*)d_in[11]; const float* c3b1 = (const float*)d_in[12];
    const float* c3w2 = (const float*)d_in[13]; const float* c3b2 = (const float*)d_in[14];
    const float* nw1 = (const float*)d_in[15];  const float* nb1 = (const float*)d_in[16];
    const float* nw2 = (const float*)d_in[17];  const float* nb2 = (const float*)d_in[18];
    const float* nw3 = (const float*)d_in[19];  const float* nb3 = (const float*)d_in[20];
    const float* ew1 = (const float*)d_in[21];  const float* eb1 = (const float*)d_in[22];
    const float* ew2 = (const float*)d_in[23];  const float* eb2 = (const float*)d_in[24];
    const float* ew3 = (const float*)d_in[25];  const float* eb3 = (const float*)d_in[26];

    float* out_node = (float*)d_out;
    float* out_edge = out_node + (size_t)NNODE * 32;

    const int* row = edge_index;
    const int* col = edge_index + NEDGE;

    float *e1, *e2, *n1, *n2, *ns1, *ns2, *ns3;
    cudaGetSymbolAddress((void**)&e1, g_e1);
    cudaGetSymbolAddress((void**)&e2, g_e2);
    cudaGetSymbolAddress((void**)&n1, g_n1);
    cudaGetSymbolAddress((void**)&n2, g_n2);
    cudaGetSymbolAddress((void**)&ns1, g_ns1);
    cudaGetSymbolAddress((void**)&ns2, g_ns2);
    cudaGetSymbolAddress((void**)&ns3, g_ns3);

    // dynamic smem (floats): cs 8224 | w1 CIN*32 | w2 1024 | b 64 | [ms 3168] | idx 512
    const int SM1 = (8224 + 96 * 32 + 1024 + 64 + 512) * 4;             // 51584
    const int SM2 = (8224 + 128 * 32 + 1024 + 64 + 512) * 4;            // 55680
    const int SM3 = (8224 + 160 * 32 + 1024 + 64 + 3168 + 512) * 4;     // 72448
    cudaFuncSetAttribute(conv_kernel<96, false>,  cudaFuncAttributeMaxDynamicSharedMemorySize, SM1);
    cudaFuncSetAttribute(conv_kernel<128, false>, cudaFuncAttributeMaxDynamicSharedMemorySize, SM2);
    cudaFuncSetAttribute(conv_kernel<160, true>,  cudaFuncAttributeMaxDynamicSharedMemorySize, SM3);

    const int EB = NEDGE / 256;           // 6250
    const int NB32 = NNODE * 32 / 256;    // 6250

    zero_kernel<<<1024, 256>>>();
    count_kernel<<<EB, 256>>>(row);
    inv_kernel<<<(NNODE + 255) / 256, 256>>>();

    conv_kernel<96, false><<<EB, 256, SM1>>>(
        node_attr, edge_attr, nullptr, nullptr, row, col,
        c1w1, c1b1, c1w2, c1b2,
        nullptr, nullptr, nullptr, nullptr, nullptr, nullptr,
        ns1, e1);
    node_lr_kernel<<<NB32, 256>>>(ns1, n1);

    conv_kernel<128, false><<<EB, 256, SM2>>>(
        n1, e1, edge_attr, nullptr, row, col,
        c2w1, c2b1, c2w2, c2b2,
        nullptr, nullptr, nullptr, nullptr, nullptr, nullptr,
        ns2, e2);
    node_lr_kernel<<<NB32, 256>>>(ns2, n2);

    conv_kernel<160, true><<<EB, 256, SM3>>>(
        n2, e2, e1, edge_attr, row, col,
        c3w1, c3b1, c3w2, c3b2,
        ew1, eb1, ew2, eb2, ew3, eb3,
        ns3, out_edge);

    node_final_kernel<<<(NNODE + 255) / 256, 256>>>(
        ns3, nw1, nb1, nw2, nb2, nw3, nb3, out_node);
}

// round 6
// speedup vs baseline: 1.4390x; 1.0002x over previous
#include <cuda_runtime.h>
#include <cstdint>

#define NNODE 50000
#define NEDGE 1600000

typedef unsigned long long ull;

// ---------------- device scratch (no allocations allowed) ----------------
__device__ float g_e1[(size_t)NEDGE * 32];   // lrelu(e1)
__device__ float g_e2[(size_t)NEDGE * 32];   // lrelu(e2)
__device__ float g_n1[(size_t)NNODE * 32];
__device__ float g_n2[(size_t)NNODE * 32];
__device__ float g_ns1[(size_t)NNODE * 32];
__device__ float g_ns2[(size_t)NNODE * 32];
__device__ float g_ns3[(size_t)NNODE * 32];
__device__ float g_inv[NNODE];
__device__ int   g_cnt[NNODE];

__device__ __forceinline__ float lrelu(float x) { return x > 0.f ? x : 0.2f * x; }

__device__ __forceinline__ ull bcast2(float v) {
    ull r; unsigned u = __float_as_uint(v);
    asm("mov.b64 %0, {%1,%1};" : "=l"(r) : "r"(u));
    return r;
}
__device__ __forceinline__ void unpack2(ull v, float& a, float& b) {
    unsigned lo, hi;
    asm("mov.b64 {%0,%1}, %2;" : "=r"(lo), "=r"(hi) : "l"(v));
    a = __uint_as_float(lo); b = __uint_as_float(hi);
}
// acc[16] packed f32x2 accumulators += hv * wrow[0..31]
__device__ __forceinline__ void fma16p(ull (&acc)[16], ull h2, const float* __restrict__ wrow) {
    const ulonglong2* w = (const ulonglong2*)wrow;
#pragma unroll
    for (int j = 0; j < 8; j++) {
        ulonglong2 wv = w[j];
        asm("fma.rn.f32x2 %0, %1, %2, %0;" : "+l"(acc[2 * j + 0]) : "l"(h2), "l"(wv.x));
        asm("fma.rn.f32x2 %0, %1, %2, %0;" : "+l"(acc[2 * j + 1]) : "l"(h2), "l"(wv.y));
    }
}

// ---------------- setup kernels ----------------
__global__ void zero_kernel() {
    int stride = gridDim.x * blockDim.x;
    int i0 = blockIdx.x * blockDim.x + threadIdx.x;
    for (int v = i0; v < NNODE * 32; v += stride) {
        g_ns1[v] = 0.f; g_ns2[v] = 0.f; g_ns3[v] = 0.f;
    }
    for (int v = i0; v < NNODE; v += stride) g_cnt[v] = 0;
}

__global__ void count_kernel(const int* __restrict__ row) {
    int e = blockIdx.x * 256 + threadIdx.x;
    atomicAdd(&g_cnt[row[e]], 1);
}

__global__ void inv_kernel() {
    int v = blockIdx.x * 256 + threadIdx.x;
    if (v < NNODE) g_inv[v] = 1.f / fmaxf((float)g_cnt[v], 1.f);
}

// ---------------- fused edge-conv kernel ----------------
// One thread per edge, 256 edges/block. All inputs staged through a shared
// transpose buffer (coalesced GMEM access both for edge features and node
// gathers). GEMM accumulation in packed f32x2.
template <int CIN, bool FUSE_MLP>
__global__ __launch_bounds__(256, 3)
void conv_kernel(const float* __restrict__ xn,
                 const float* __restrict__ ef0,
                 const float* __restrict__ ef1,
                 const float* __restrict__ ef2,
                 const int* __restrict__ ridx,
                 const int* __restrict__ cidx,
                 const float* __restrict__ w1, const float* __restrict__ b1,
                 const float* __restrict__ w2, const float* __restrict__ b2,
                 const float* __restrict__ mw1, const float* __restrict__ mb1,
                 const float* __restrict__ mw2, const float* __restrict__ mb2,
                 const float* __restrict__ mw3, const float* __restrict__ mb3,
                 float* __restrict__ nsum,
                 float* __restrict__ eout) {
    constexpr int NB = CIN / 32;
    constexpr int SP = 257;                // conflict-free transpose stride
    constexpr int MSZ = FUSE_MLP ? 3168 : 0;
    extern __shared__ float sm[];
    float* cs  = sm;                       // 32 * 257
    float* w1s = sm + 32 * SP;             // CIN*32 (16B aligned)
    float* w2s = w1s + CIN * 32;           // 1024
    float* b1s = w2s + 1024;               // 32 (8B aligned)
    float* b2s = b1s + 32;                 // 32
    float* ms  = b2s + 32;                 // fused MLP weights
    int*   rs  = (int*)(ms + MSZ);         // 256
    int*   cls = rs + 256;                 // 256

    const int tid = threadIdx.x;
    const size_t tile0 = (size_t)blockIdx.x * 256;
    const int e = (int)(tile0 + tid);

    // stage weights + this block's indices
    for (int v = tid; v < CIN * 32; v += 256) w1s[v] = w1[v];
    for (int v = tid; v < 1024; v += 256)     w2s[v] = w2[v];
    if (tid < 32) { b1s[tid] = b1[tid]; b2s[tid] = b2[tid]; }
    if constexpr (FUSE_MLP) {
        for (int v = tid; v < 1024; v += 256) {
            ms[v] = mw1[v]; ms[1056 + v] = mw2[v]; ms[2112 + v] = mw3[v];
        }
        if (tid < 32) { ms[1024 + tid] = mb1[tid]; ms[2080 + tid] = mb2[tid]; ms[3136 + tid] = mb3[tid]; }
    }
    const int r = ridx[e];
    rs[tid] = r;
    cls[tid] = cidx[e];
    __syncthreads();

    ull acc[16];
    {
        const ull* bp = (const ull*)b1s;
#pragma unroll
        for (int j = 0; j < 16; j++) acc[j] = bp[j];
    }

    const float* efp[3] = { ef0, ef1, ef2 };

    for (int b = 0; b < NB; b++) {
        __syncthreads();
        if (b < 2) {
            // warp-coalesced gather: one 128B node row per warp-iteration
            const int* sidx = (b == 0) ? rs : cls;
            const int ch = tid & 31;
            const int e0 = tid >> 5;
#pragma unroll
            for (int it = 0; it < 32; it++) {
                int eidx = e0 + it * 8;
                cs[ch * SP + eidx] = xn[(size_t)sidx[eidx] * 32 + ch];
            }
        } else {
            // coalesced vector stage of 256x32 edge-feature chunk
            const float4* src = (const float4*)(efp[b - 2] + tile0 * 32);
#pragma unroll
            for (int it = 0; it < 8; it++) {
                int v = tid + it * 256;
                float4 f = src[v];
                int m = 4 * v;
                int eidx = m >> 5;
                int ch = m & 31;
                cs[(ch + 0) * SP + eidx] = f.x;
                cs[(ch + 1) * SP + eidx] = f.y;
                cs[(ch + 2) * SP + eidx] = f.z;
                cs[(ch + 3) * SP + eidx] = f.w;
            }
        }
        __syncthreads();
#pragma unroll
        for (int i = 0; i < 32; i++) {
            ull h2 = bcast2(cs[i * SP + tid]);
            fma16p(acc, h2, &w1s[(b * 32 + i) * 32]);
        }
    }

    // stage relu(hidden) into this thread's private shared column (no sync needed)
#pragma unroll
    for (int j = 0; j < 16; j++) {
        float a0, a1; unpack2(acc[j], a0, a1);
        cs[(2 * j + 0) * SP + tid] = fmaxf(a0, 0.f);
        cs[(2 * j + 1) * SP + tid] = fmaxf(a1, 0.f);
    }

    // second linear
    ull out2[16];
    {
        const ull* bp = (const ull*)b2s;
#pragma unroll
        for (int j = 0; j < 16; j++) out2[j] = bp[j];
    }
#pragma unroll
    for (int k = 0; k < 32; k++) {
        ull h2 = bcast2(cs[k * SP + tid]);
        fma16p(out2, h2, &w2s[k * 32]);
    }

    float o[32];
#pragma unroll
    for (int j = 0; j < 16; j++) unpack2(out2[j], o[2 * j], o[2 * j + 1]);

    // scatter raw edge output to node sums (vectorized L2 reductions)
    {
        float* np = nsum + (size_t)r * 32;
#pragma unroll
        for (int j4 = 0; j4 < 8; j4++) {
            asm volatile("red.global.add.v4.f32 [%0], {%1,%2,%3,%4};"
                         :: "l"(np + j4 * 4),
                            "f"(o[j4 * 4 + 0]), "f"(o[j4 * 4 + 1]),
                            "f"(o[j4 * 4 + 2]), "f"(o[j4 * 4 + 3])
                         : "memory");
        }
    }

#pragma unroll
    for (int j = 0; j < 32; j++) o[j] = lrelu(o[j]);

    if constexpr (FUSE_MLP) {
        // write current edge value to private column, run 3 fused 32x32 layers
#pragma unroll
        for (int j = 0; j < 32; j++) cs[j * SP + tid] = o[j];
        const float* mws[3] = { ms, ms + 1056, ms + 2112 };
        const float* mbs[3] = { ms + 1024, ms + 2080, ms + 3136 };
#pragma unroll
        for (int L = 0; L < 3; L++) {
            ull t2[16];
            const ull* bp = (const ull*)mbs[L];
#pragma unroll
            for (int j = 0; j < 16; j++) t2[j] = bp[j];
#pragma unroll
            for (int k = 0; k < 32; k++) {
                ull h2 = bcast2(cs[k * SP + tid]);
                fma16p(t2, h2, mws[L] + k * 32);
            }
#pragma unroll
            for (int j = 0; j < 16; j++) {
                float a0, a1; unpack2(t2[j], a0, a1);
                if (L < 2) { a0 = lrelu(a0); a1 = lrelu(a1); }
                cs[(2 * j + 0) * SP + tid] = a0;
                cs[(2 * j + 1) * SP + tid] = a1;
            }
        }
    } else {
#pragma unroll
        for (int j = 0; j < 32; j++) cs[j * SP + tid] = o[j];
    }

    // coalesced vectorized store from transpose buffer
    __syncthreads();
    float4* dst = (float4*)(eout + tile0 * 32);
#pragma unroll
    for (int it = 0; it < 8; it++) {
        int v = tid + it * 256;
        int m = 4 * v;
        int eidx = m >> 5;
        int ch = m & 31;
        float4 f;
        f.x = cs[(ch + 0) * SP + eidx];
        f.y = cs[(ch + 1) * SP + eidx];
        f.z = cs[(ch + 2) * SP + eidx];
        f.w = cs[(ch + 3) * SP + eidx];
        dst[v] = f;
    }
}

// ---------------- node-side kernels ----------------
__global__ void node_lr_kernel(const float* __restrict__ ns, float* __restrict__ nout) {
    int idx = blockIdx.x * 256 + threadIdx.x;     // grid sized exactly N*32/256
    float v = ns[idx] * g_inv[idx >> 5];
    nout[idx] = lrelu(v);
}

__global__ __launch_bounds__(256)
void node_final_kernel(const float* __restrict__ ns,
                       const float* __restrict__ nw1, const float* __restrict__ nb1,
                       const float* __restrict__ nw2, const float* __restrict__ nb2,
                       const float* __restrict__ nw3, const float* __restrict__ nb3,
                       float* __restrict__ out) {
    __shared__ float ws1[1024], ws2[1024], ws3[1024], bs1[32], bs2[32], bs3[32];
    int tid = threadIdx.x;
    for (int v = tid; v < 1024; v += 256) { ws1[v] = nw1[v]; ws2[v] = nw2[v]; ws3[v] = nw3[v]; }
    if (tid < 32) { bs1[tid] = nb1[tid]; bs2[tid] = nb2[tid]; bs3[tid] = nb3[tid]; }
    __syncthreads();

    int v = blockIdx.x * 256 + tid;
    if (v >= NNODE) return;

    float inv = g_inv[v];
    float x[32];
#pragma unroll
    for (int j4 = 0; j4 < 8; j4++) {
        float4 a = *(const float4*)(ns + (size_t)v * 32 + j4 * 4);
        x[j4 * 4 + 0] = lrelu(a.x * inv);
        x[j4 * 4 + 1] = lrelu(a.y * inv);
        x[j4 * 4 + 2] = lrelu(a.z * inv);
        x[j4 * 4 + 3] = lrelu(a.w * inv);
    }

    ull t2[16], u2[16];
    {
        const ull* bp = (const ull*)bs1;
#pragma unroll
        for (int j = 0; j < 16; j++) t2[j] = bp[j];
    }
#pragma unroll
    for (int k = 0; k < 32; k++) fma16p(t2, bcast2(x[k]), ws1 + k * 32);
#pragma unroll
    for (int j = 0; j < 16; j++) { float a0, a1; unpack2(t2[j], a0, a1); x[2 * j] = lrelu(a0); x[2 * j + 1] = lrelu(a1); }
    {
        const ull* bp = (const ull*)bs2;
#pragma unroll
        for (int j = 0; j < 16; j++) u2[j] = bp[j];
    }
#pragma unroll
    for (int k = 0; k < 32; k++) fma16p(u2, bcast2(x[k]), ws2 + k * 32);
#pragma unroll
    for (int j = 0; j < 16; j++) { float a0, a1; unpack2(u2[j], a0, a1); x[2 * j] = lrelu(a0); x[2 * j + 1] = lrelu(a1); }
    {
        const ull* bp = (const ull*)bs3;
#pragma unroll
        for (int j = 0; j < 16; j++) t2[j] = bp[j];
    }
#pragma unroll
    for (int k = 0; k < 32; k++) fma16p(t2, bcast2(x[k]), ws3 + k * 32);
#pragma unroll
    for (int j = 0; j < 16; j++) unpack2(t2[j], x[2 * j], x[2 * j + 1]);

    float* dst = out + (size_t)v * 32;
#pragma unroll
    for (int j4 = 0; j4 < 8; j4++) {
        float4 a = make_float4(x[j4 * 4 + 0], x[j4 * 4 + 1], x[j4 * 4 + 2], x[j4 * 4 + 3]);
        *(float4*)(dst + j4 * 4) = a;
    }
}

// ---------------- launch ----------------
extern "C" void kernel_launch(void* const* d_in, const int* in_sizes, int n_in,
                              void* d_out, int out_size) {
    const float* node_attr = (const float*)d_in[0];
    const float* edge_attr = (const float*)d_in[1];
    const int*   edge_index = (const int*)d_in[2];
    const float* c1w1 = (const float*)d_in[3];  const float* c1b1 = (const float*)d_in[4];
    const float* c1w2 = (const float*)d_in[5];  const float* c1b2 = (const float*)d_in[6];
    const float* c2w1 = (const float*)d_in[7];  const float* c2b1 = (const float*)d_in[8];
    const float* c2w2 = (const float*)d_in[9];  const float* c2b2 = (const float*)d_in[10];
    const float* c3w1 = (const float*)d_in[11]; const float* c3b1 = (const float*)d_in[12];
    const float* c3w2 = (const float*)d_in[13]; const float* c3b2 = (const float*)d_in[14];
    const float* nw1 = (const float*)d_in[15];  const float* nb1 = (const float*)d_in[16];
    const float* nw2 = (const float*)d_in[17];  const float* nb2 = (const float*)d_in[18];
    const float* nw3 = (const float*)d_in[19];  const float* nb3 = (const float*)d_in[20];
    const float* ew1 = (const float*)d_in[21];  const float* eb1 = (const float*)d_in[22];
    const float* ew2 = (const float*)d_in[23];  const float* eb2 = (const float*)d_in[24];
    const float* ew3 = (const float*)d_in[25];  const float* eb3 = (const float*)d_in[26];

    float* out_node = (float*)d_out;
    float* out_edge = out_node + (size_t)NNODE * 32;

    const int* row = edge_index;
    const int* col = edge_index + NEDGE;

    float *e1, *e2, *n1, *n2, *ns1, *ns2, *ns3;
    cudaGetSymbolAddress((void**)&e1, g_e1);
    cudaGetSymbolAddress((void**)&e2, g_e2);
    cudaGetSymbolAddress((void**)&n1, g_n1);
    cudaGetSymbolAddress((void**)&n2, g_n2);
    cudaGetSymbolAddress((void**)&ns1, g_ns1);
    cudaGetSymbolAddress((void**)&ns2, g_ns2);
    cudaGetSymbolAddress((void**)&ns3, g_ns3);

    // dynamic smem (floats): cs 8224 | w1 CIN*32 | w2 1024 | b 64 | [ms 3168] | idx 512
    const int SM1 = (8224 + 96 * 32 + 1024 + 64 + 512) * 4;             // 51584
    const int SM2 = (8224 + 128 * 32 + 1024 + 64 + 512) * 4;            // 55680
    const int SM3 = (8224 + 160 * 32 + 1024 + 64 + 3168 + 512) * 4;     // 72448
    cudaFuncSetAttribute(conv_kernel<96, false>,  cudaFuncAttributeMaxDynamicSharedMemorySize, SM1);
    cudaFuncSetAttribute(conv_kernel<128, false>, cudaFuncAttributeMaxDynamicSharedMemorySize, SM2);
    cudaFuncSetAttribute(conv_kernel<160, true>,  cudaFuncAttributeMaxDynamicSharedMemorySize, SM3);

    const int EB = NEDGE / 256;           // 6250
    const int NB32 = NNODE * 32 / 256;    // 6250

    zero_kernel<<<1024, 256>>>();
    count_kernel<<<EB, 256>>>(row);
    inv_kernel<<<(NNODE + 255) / 256, 256>>>();

    conv_kernel<96, false><<<EB, 256, SM1>>>(
        node_attr, edge_attr, nullptr, nullptr, row, col,
        c1w1, c1b1, c1w2, c1b2,
        nullptr, nullptr, nullptr, nullptr, nullptr, nullptr,
        ns1, e1);
    node_lr_kernel<<<NB32, 256>>>(ns1, n1);

    conv_kernel<128, false><<<EB, 256, SM2>>>(
        n1, e1, edge_attr, nullptr, row, col,
        c2w1, c2b1, c2w2, c2b2,
        nullptr, nullptr, nullptr, nullptr, nullptr, nullptr,
        ns2, e2);
    node_lr_kernel<<<NB32, 256>>>(ns2, n2);

    conv_kernel<160, true><<<EB, 256, SM3>>>(
        n2, e2, e1, edge_attr, row, col,
        c3w1, c3b1, c3w2, c3b2,
        ew1, eb1, ew2, eb2, ew3, eb3,
        ns3, out_edge);

    node_final_kernel<<<(NNODE + 255) / 256, 256>>>(
        ns3, nw1, nb1, nw2, nb2, nw3, nb3, out_node);
}